// round 17
// baseline (speedup 1.0000x reference)
#include <cuda_runtime.h>
#include <cuda_fp16.h>
#include <stdint.h>

#define B_SZ     4096
#define D0       1024
#define D1       8192
#define D2       8192
#define D3       10240
#define NNEUR    (D1 + D2 + D3)     // 26624
#define KCLS     10
#define GRP      (D3 / KCLS)        // 1024
#define TAU      30.0f
#define ROWS     4
#define NTHREADS 1024
#define CELLS    256                // 16 a-residues x 16 b-residues (mod 16)
#define SCNSTR   72                 // 64 virtual warps + pad
// paired metadata bases (in pair units)
#define PB1      0                  // layer1: 4096 pairs
#define PB2      4096               // layer2: 4096 pairs
#define PB3      8192               // layer3: 5120 pairs

// -------- inverse perms (orig -> dealt pos, layer-local) --------
__device__ uint16_t d_inv1[D1];
__device__ uint16_t d_inv2[D2];
// -------- final metadata, PAIRED layout --------
__device__ __align__(16) uint32_t g_pidx[NNEUR];       // packed ia|ib<<16
__device__ __align__(16) uint32_t g_pcoef[NNEUR * 2];  // {c01,c23} per neuron

__constant__ float OPC[16][4] = {
    {0.f, 0.f, 0.f, 0.f}, {0.f, 0.f, 0.f, 1.f}, {0.f, 1.f, 0.f, -1.f}, {0.f, 1.f, 0.f, 0.f},
    {0.f, 0.f, 1.f, -1.f}, {0.f, 0.f, 1.f, 0.f}, {0.f, 1.f, 1.f, -2.f}, {0.f, 1.f, 1.f, -1.f},
    {1.f, -1.f, -1.f, 1.f}, {1.f, -1.f, -1.f, 2.f}, {1.f, 0.f, -1.f, 0.f}, {1.f, 0.f, -1.f, 1.f},
    {1.f, -1.f, 0.f, 0.f}, {1.f, -1.f, 0.f, 1.f}, {1.f, 0.f, 0.f, -1.f}, {1.f, 0.f, 0.f, 0.f}};

// paired slot mapping: (layer-local dealt pos) -> (pair slot, half)
// layers 1/2: pairs (p, p+1024) within 2048-windows; layer 3: (p, p+512) within 1024.
__device__ __forceinline__ void pair_slot(int layer, int lpos, int& slot, int& half)
{
    if (layer < 2) { slot = (lpos >> 11) * 1024 + (lpos & 1023); half = (lpos >> 10) & 1; }
    else           { slot = (lpos >> 10) * 512  + (lpos & 511);  half = (lpos >> 9) & 1; }
}

// ---- ONE parallel build launch: 18 independent CTAs -------------------------
// L1/L2: CHUNK=2048 (CAP=8, ITEMS=2/thread) -> seat rate ~90.5%.
// L3:    CHUNK=1024 (CAP=4, ITEMS=1) -- perm must stay within each class group.
// Residues from raw index chains (exact iff source seated):
//   L1: ia1[j]&15  L2: ia1[ia2[j]]&15  L3: ia1[ia2[ia3[j]]]&15
// Deal window (32 slots) covers each a-residue 2x, b-residue 2x regardless of CAP.
__global__ void __launch_bounds__(1024, 1)
build_kernel(const float* __restrict__ w1, const float* __restrict__ w2,
             const float* __restrict__ w3,
             const int* __restrict__ ia1, const int* __restrict__ ib1,
             const int* __restrict__ ia2, const int* __restrict__ ib2,
             const int* __restrict__ ia3, const int* __restrict__ ib3)
{
    __shared__ uint16_t off[CELLS * SCNSTR];   // per (cell, vwarp) counts -> exclusive
    __shared__ uint16_t chb[CELLS * 4];        // per (cell, 16-vwarp chunk) bases
    __shared__ uint16_t csize[CELLS], exo[CELLS], ufo[CELLS];
    __shared__ uint16_t ufp[2048];
    __shared__ int wte[8], wtu[8];

    const int tid  = threadIdx.x;
    const int lane = tid & 31;
    const int w    = tid >> 5;
    const uint32_t ltm = (1u << lane) - 1u;

    const int blk   = blockIdx.x;              // 0..17
    const int layer = (blk < 4) ? 0 : ((blk < 8) ? 1 : 2);
    const int items = (layer < 2) ? 2 : 1;
    const int cap   = (layer < 2) ? 8 : 4;
    const int baseL = (layer == 0) ? blk * 2048
                    : (layer == 1) ? (blk - 4) * 2048
                                   : (blk - 8) * 1024;

    for (int i = tid; i < CELLS * SCNSTR / 2; i += NTHREADS)
        reinterpret_cast<uint32_t*>(off)[i] = 0;
    __syncthreads();

    // ---- per-item metadata + residues + counts ----
    int mcell[2], mlr[2];
    int mia[2], mib[2];
    uint32_t mc01[2], mc23[2];
#pragma unroll
    for (int k = 0; k < 2; k++) {
        if (k >= items) break;
        int j = baseL + k * 1024 + tid;
        int ia, ib; const float* wp;
        uint32_t ra, rb;
        if (layer == 0) {
            ia = __ldg(&ia1[j]); ib = __ldg(&ib1[j]); wp = w1 + (size_t)j * 16;
            ra = (uint32_t)ia & 15u; rb = (uint32_t)ib & 15u;
        } else if (layer == 1) {
            ia = __ldg(&ia2[j]); ib = __ldg(&ib2[j]); wp = w2 + (size_t)j * 16;
            ra = (uint32_t)__ldg(&ia1[ia]) & 15u;
            rb = (uint32_t)__ldg(&ia1[ib]) & 15u;
        } else {
            ia = __ldg(&ia3[j]); ib = __ldg(&ib3[j]); wp = w3 + (size_t)j * 16;
            ra = (uint32_t)__ldg(&ia1[__ldg(&ia2[ia])]) & 15u;
            rb = (uint32_t)__ldg(&ia1[__ldg(&ia2[ib])]) & 15u;
        }
        mia[k] = ia; mib[k] = ib;

        float v[16]; float m = -3.4e38f;
#pragma unroll
        for (int i = 0; i < 16; i++) { v[i] = wp[i]; m = fmaxf(m, v[i]); }
        float s = 0.f;
#pragma unroll
        for (int i = 0; i < 16; i++) { v[i] = __expf(v[i] - m); s += v[i]; }
        float inv = 1.f / s;
        float c0 = 0.f, c1 = 0.f, c2 = 0.f, c3 = 0.f;
#pragma unroll
        for (int i = 0; i < 16; i++) {
            float p = v[i] * inv;
            c0 = fmaf(p, OPC[i][0], c0);
            c1 = fmaf(p, OPC[i][1], c1);
            c2 = fmaf(p, OPC[i][2], c2);
            c3 = fmaf(p, OPC[i][3], c3);
        }
        __half2 h01 = __floats2half2_rn(c0, c1);
        __half2 h23 = __floats2half2_rn(c2, c3);
        mc01[k] = *reinterpret_cast<uint32_t*>(&h01);
        mc23[k] = *reinterpret_cast<uint32_t*>(&h23);

        int cell = (int)(ra * 16u + rb);
        uint32_t mask = __match_any_sync(0xffffffffu, cell);
        mcell[k] = cell;
        mlr[k]   = __popc(mask & ltm);
        if ((mask & ltm) == 0)
            off[cell * SCNSTR + (k * 32 + w)] = (uint16_t)__popc(mask);
    }
    __syncthreads();

    {   // phase 1: per-(cell, 16-vwarp chunk) exclusive scan (VW=64, 4 chunks)
        int c  = tid >> 2;
        int ch = tid & 3;
        int bo = c * SCNSTR + ch * 16;
        uint16_t run = 0;
#pragma unroll
        for (int i = 0; i < 16; i++) {
            uint16_t t = off[bo + i];
            off[bo + i] = run;
            run = (uint16_t)(run + t);
        }
        chb[c * 4 + ch] = run;
    }
    __syncthreads();

    if (tid < CELLS) {   // phase 2: per-cell combine
        int c = tid; uint16_t bb = 0;
#pragma unroll
        for (int ch = 0; ch < 4; ch++) {
            uint16_t t = chb[c * 4 + ch];
            chb[c * 4 + ch] = bb;
            bb = (uint16_t)(bb + t);
        }
        csize[c] = bb;
        exo[c] = (bb > cap) ? (uint16_t)(bb - cap) : 0;
        ufo[c] = (bb < cap) ? (uint16_t)(cap - bb) : 0;
    }
    __syncthreads();

    {   // inclusive scans over 256 cells via warp shuffles
        int e = 0, u = 0;
        if (tid < CELLS) {
            e = exo[tid]; u = ufo[tid];
#pragma unroll
            for (int o = 1; o < 32; o <<= 1) {
                int pe = __shfl_up_sync(0xffffffffu, e, o);
                int pu = __shfl_up_sync(0xffffffffu, u, o);
                if (lane >= o) { e += pe; u += pu; }
            }
            if (lane == 31) { wte[w] = e; wtu[w] = u; }
        }
        __syncthreads();
        if (tid == 0) {
            int be = 0, bu = 0;
#pragma unroll
            for (int i = 0; i < 8; i++) {
                int te = wte[i], tu = wtu[i];
                wte[i] = be; wtu[i] = bu;
                be += te; bu += tu;
            }
        }
        __syncthreads();
        if (tid < CELLS) {
            exo[tid] = (uint16_t)(e + wte[w]);
            ufo[tid] = (uint16_t)(u + wtu[w]);
        }
    }
    __syncthreads();

    if (tid < CELLS) {   // emit unfilled dealt positions, grouped by cell
        int c = tid, t = c >> 4, ss = c & 15;
        int sz  = csize[c];
        int ufc = (sz < cap) ? cap - sz : 0;
        int ub  = ufo[c] - ufc;
        for (int mm = sz; mm < cap; mm++)
            ufp[ub + (mm - sz)] = (uint16_t)((((ss - t) & 15) + 16 * mm) * 16 + t);
    }
    __syncthreads();

    // ---- assign positions + publish paired metadata (raw indices) ----
    int pb = (layer == 0) ? PB1 : ((layer == 1) ? PB2 : PB3);
#pragma unroll
    for (int k = 0; k < 2; k++) {
        if (k >= items) break;
        int j = baseL + k * 1024 + tid;
        int cell = mcell[k];
        int v = k * 32 + w;
        int grank = off[cell * SCNSTR + v] + chb[cell * 4 + (v >> 4)] + mlr[k];
        int t = cell >> 4, ss = cell & 15;
        int p;
        if (grank < cap) {
            p = (((ss - t) & 15) + 16 * grank) * 16 + t;
        } else {
            int exc = csize[cell] - cap;
            int exb = exo[cell] - exc;
            p = ufp[exb + (grank - cap)];
        }
        int lpos = baseL + p;

        if (layer == 0)      d_inv1[j] = (uint16_t)lpos;
        else if (layer == 1) d_inv2[j] = (uint16_t)lpos;

        int slot, half;
        pair_slot(layer, lpos, slot, half);
        g_pidx[(pb + slot) * 2 + half] = (uint32_t)mia[k] | ((uint32_t)mib[k] << 16);
        g_pcoef[(pb + slot) * 4 + half * 2 + 0] = mc01[k];
        g_pcoef[(pb + slot) * 4 + half * 2 + 1] = mc23[k];
    }
}

// ---- remap: translate L2/L3 stored raw indices into dealt position space ---
__global__ void remap_kernel()
{
    int k = blockIdx.x * blockDim.x + threadIdx.x;
    int idx = PB2 * 2 + k;
    if (idx >= NNEUR) return;
    uint32_t pk = g_pidx[idx];
    uint32_t a, b;
    if (idx < PB3 * 2) { a = d_inv1[pk & 0xffffu]; b = d_inv1[pk >> 16]; }
    else               { a = d_inv2[pk & 0xffffu]; b = d_inv2[pk >> 16]; }
    g_pidx[idx] = a | (b << 16);
}

// -------- main kernel: UNCHANGED from R16 winner -----------------------------

__device__ __forceinline__ uint2 one_neuron(uint32_t u01, uint32_t u23,
                                            uint2 av, uint2 bv)
{
    float2 c01 = __half22float2(*reinterpret_cast<const __half2*>(&u01));
    float2 c23 = __half22float2(*reinterpret_cast<const __half2*>(&u23));
    uint2 o;
#pragma unroll
    for (int r = 0; r < 2; r++) {
        uint32_t ua = (r == 0) ? av.x : av.y;
        uint32_t ub = (r == 0) ? bv.x : bv.y;
        float2 a = __half22float2(*reinterpret_cast<const __half2*>(&ua));
        float2 b = __half22float2(*reinterpret_cast<const __half2*>(&ub));
        float o0 = fmaf(fmaf(c23.y, b.x, c01.y), a.x, fmaf(c23.x, b.x, c01.x));
        float o1 = fmaf(fmaf(c23.y, b.y, c01.y), a.y, fmaf(c23.x, b.y, c01.x));
        __half2 h = __floats2half2_rn(o0, o1);
        uint32_t uh = *reinterpret_cast<uint32_t*>(&h);
        if (r == 0) o.x = uh; else o.y = uh;
    }
    return o;
}

struct PairIn {
    uint2 idx;
    uint4 coef;
    uint2 a0, b0, a1, b1;
};

__device__ __forceinline__ void fetch_pair(const uint2* __restrict__ src,
                                           int slot, PairIn& p)
{
    p.idx  = __ldg(reinterpret_cast<const uint2*>(g_pidx) + slot);
    p.coef = __ldg(reinterpret_cast<const uint4*>(g_pcoef) + slot);
    p.a0 = src[p.idx.x & 0xffffu];
    p.b0 = src[p.idx.x >> 16];
    p.a1 = src[p.idx.y & 0xffffu];
    p.b1 = src[p.idx.y >> 16];
}

__device__ __forceinline__ void run_layer(const uint2* __restrict__ src,
                                          uint2* __restrict__ dst,
                                          int pairBase, int tid)
{
    const int iters = D1 / 2048;                  // 4
    PairIn cur, nxt;
    fetch_pair(src, pairBase + tid, cur);
#pragma unroll
    for (int it = 0; it < iters - 1; it++) {
        fetch_pair(src, pairBase + (it + 1) * 1024 + tid, nxt);
        int pos0 = it * 2048 + tid;
        dst[pos0]        = one_neuron(cur.coef.x, cur.coef.y, cur.a0, cur.b0);
        dst[pos0 + 1024] = one_neuron(cur.coef.z, cur.coef.w, cur.a1, cur.b1);
        cur = nxt;
    }
    int pos0 = (iters - 1) * 2048 + tid;
    dst[pos0]        = one_neuron(cur.coef.x, cur.coef.y, cur.a0, cur.b0);
    dst[pos0 + 1024] = one_neuron(cur.coef.z, cur.coef.w, cur.a1, cur.b1);
}

__global__ void __launch_bounds__(NTHREADS, 1)
diff_logic_main(const float* __restrict__ x, float* __restrict__ out)
{
    extern __shared__ __align__(16) uint32_t smem_raw[];
    uint2* xs = reinterpret_cast<uint2*>(smem_raw);
    uint2* h1 = xs + D0;
    uint2* h2 = h1 + D1;
    float* wacc = reinterpret_cast<float*>(h2 + D2);   // [KCLS*16][ROWS]

    const int tid  = threadIdx.x;
    const int lane = tid & 31;
    const int row0 = blockIdx.x * ROWS;

    {
        int col = tid;                            // D0 == NTHREADS
        float v0 = __ldg(&x[(size_t)(row0 + 0) * D0 + col]);
        float v1 = __ldg(&x[(size_t)(row0 + 1) * D0 + col]);
        float v2 = __ldg(&x[(size_t)(row0 + 2) * D0 + col]);
        float v3 = __ldg(&x[(size_t)(row0 + 3) * D0 + col]);
        __half2 p0 = __floats2half2_rn(v0, v1);
        __half2 p1 = __floats2half2_rn(v2, v3);
        uint2 slot;
        slot.x = *reinterpret_cast<uint32_t*>(&p0);
        slot.y = *reinterpret_cast<uint32_t*>(&p1);
        xs[col] = slot;
    }
    __syncthreads();

    run_layer(xs, h1, PB1, tid);
    __syncthreads();
    run_layer(h1, h2, PB2, tid);
    __syncthreads();

#pragma unroll
    for (int it = 0; it < 5; it++) {
        int q     = it * 1024 + tid;              // global pair index [0,5120)
        int group = q >> 9;
        int wig   = (q & 511) >> 5;               // warp-in-group [0,16)
        PairIn n;
        fetch_pair(h2, PB3 + q, n);

        float acc[ROWS];
        {
            float2 c01 = __half22float2(*reinterpret_cast<const __half2*>(&n.coef.x));
            float2 c23 = __half22float2(*reinterpret_cast<const __half2*>(&n.coef.y));
#pragma unroll
            for (int r = 0; r < 2; r++) {
                uint32_t ua = (r == 0) ? n.a0.x : n.a0.y;
                uint32_t ub = (r == 0) ? n.b0.x : n.b0.y;
                float2 a = __half22float2(*reinterpret_cast<const __half2*>(&ua));
                float2 b = __half22float2(*reinterpret_cast<const __half2*>(&ub));
                acc[2 * r + 0] = fmaf(fmaf(c23.y, b.x, c01.y), a.x, fmaf(c23.x, b.x, c01.x));
                acc[2 * r + 1] = fmaf(fmaf(c23.y, b.y, c01.y), a.y, fmaf(c23.x, b.y, c01.x));
            }
        }
        {
            float2 c01 = __half22float2(*reinterpret_cast<const __half2*>(&n.coef.z));
            float2 c23 = __half22float2(*reinterpret_cast<const __half2*>(&n.coef.w));
#pragma unroll
            for (int r = 0; r < 2; r++) {
                uint32_t ua = (r == 0) ? n.a1.x : n.a1.y;
                uint32_t ub = (r == 0) ? n.b1.x : n.b1.y;
                float2 a = __half22float2(*reinterpret_cast<const __half2*>(&ua));
                float2 b = __half22float2(*reinterpret_cast<const __half2*>(&ub));
                acc[2 * r + 0] += fmaf(fmaf(c23.y, b.x, c01.y), a.x, fmaf(c23.x, b.x, c01.x));
                acc[2 * r + 1] += fmaf(fmaf(c23.y, b.y, c01.y), a.y, fmaf(c23.x, b.y, c01.x));
            }
        }
#pragma unroll
        for (int r = 0; r < ROWS; r++) {
#pragma unroll
            for (int off = 16; off > 0; off >>= 1)
                acc[r] += __shfl_down_sync(0xffffffffu, acc[r], off);
        }
        if (lane == 0) {
#pragma unroll
            for (int r = 0; r < ROWS; r++)
                wacc[(group * 16 + wig) * ROWS + r] = acc[r];
        }
    }
    __syncthreads();

    if (tid < KCLS * ROWS) {
        int g = tid / ROWS;
        int r = tid - g * ROWS;
        float s = 0.f;
#pragma unroll
        for (int w = 0; w < 16; w++)
            s += wacc[(g * 16 + w) * ROWS + r];
        out[(size_t)(row0 + r) * KCLS + g] = s * (1.f / TAU);
    }
}

// -----------------------------------------------------------------------------

extern "C" void kernel_launch(void* const* d_in, const int* in_sizes, int n_in,
                              void* d_out, int out_size)
{
    (void)in_sizes; (void)n_in; (void)out_size;
    const float* x  = (const float*)d_in[0];
    const float* w1 = (const float*)d_in[1];
    const float* w2 = (const float*)d_in[2];
    const float* w3 = (const float*)d_in[3];
    const int* ia1 = (const int*)d_in[4];
    const int* ib1 = (const int*)d_in[5];
    const int* ia2 = (const int*)d_in[6];
    const int* ib2 = (const int*)d_in[7];
    const int* ia3 = (const int*)d_in[8];
    const int* ib3 = (const int*)d_in[9];
    float* out = (float*)d_out;

    build_kernel<<<18, 1024>>>(w1, w2, w3, ia1, ib1, ia2, ib2, ia3, ib3);
    remap_kernel<<<(D2 + D3 + 255) / 256, 256>>>();

    size_t smem = (size_t)(D0 + D1 + D2) * sizeof(uint2)
                + (size_t)(KCLS * 16 * ROWS) * sizeof(float);   // ~144 KB
    cudaFuncSetAttribute(diff_logic_main, cudaFuncAttributeMaxDynamicSharedMemorySize, (int)smem);

    diff_logic_main<<<B_SZ / ROWS, NTHREADS, smem>>>(x, out);
}